// round 13
// baseline (speedup 1.0000x reference)
#include <cuda_runtime.h>
#include <math.h>

#define TOPK     1024
#define DFEAT    32
#define HBINS    4096          // top-12-bit histogram
#define CAND_G   2048
#define EQ_CAP   1024
#define MAXB     256
#define CPS      4             // histogram CTAs per segment
#define CPC      4             // compaction CTAs per segment
#define GPS      8             // gather CTAs per segment

__device__ unsigned g_keys[4000000];
// hist[MAXB*HBINS] ++ done[MAXB] ++ nsel[MAXB] ++ ncand[MAXB]  (one memset)
__device__ unsigned g_work[MAXB * HBINS + 3 * MAXB];
__device__ unsigned g_thresh[MAXB * 2];              // (D, kk) per segment
__device__ int      g_sel[MAXB * TOPK];
__device__ int      g_nseltot[MAXB];
__device__ unsigned g_candKey[MAXB * CAND_G];
__device__ int      g_candIdx[MAXB * CAND_G];
__device__ float    g_part[MAXB * GPS * DFEAT];

// ---------------------------------------------------------------------------
// suffix-scan of 4096-bin histogram -> bin D + in-bin rank kk. 1024 threads.
// ---------------------------------------------------------------------------
__device__ __forceinline__ void find_threshold_bin(const unsigned* s_h,
                                                   unsigned* s_w,
                                                   int tid, int lane, int wid,
                                                   int* outD, unsigned* outKK)
{
    const unsigned t4 = s_h[tid * 4] + s_h[tid * 4 + 1]
                      + s_h[tid * 4 + 2] + s_h[tid * 4 + 3];
    unsigned v = t4;
#pragma unroll
    for (int off = 1; off < 32; off <<= 1) {
        unsigned o = __shfl_down_sync(0xffffffffu, v, off);
        if (lane + off < 32) v += o;
    }
    if (lane == 0) s_w[wid] = v;
    __syncthreads();
    if (wid == 0) {
        const unsigned tv = s_w[lane];
        unsigned iv = tv;
#pragma unroll
        for (int off = 1; off < 32; off <<= 1) {
            unsigned o = __shfl_down_sync(0xffffffffu, iv, off);
            if (lane + off < 32) iv += o;
        }
        s_w[lane] = iv - tv;
    }
    __syncthreads();

    const long long E = (long long)s_w[wid] + (long long)(v - t4);
    long long r = (long long)TOPK - E;
    if (r >= 1 && r <= (long long)t4) {
        for (int d = tid * 4 + 3; d >= tid * 4; d--) {
            const unsigned c = s_h[d];
            if (r <= (long long)c) { *outD = d; *outKK = (unsigned)r; break; }
            r -= (long long)c;
        }
    }
    __syncthreads();
}

// ---------------------------------------------------------------------------
// Kernel 1: score (R10 form, 64.4us @ 82.9% DRAM). Unchanged.
// ---------------------------------------------------------------------------
__global__ void score_kernel(const float* __restrict__ x,
                             const float* __restrict__ w,
                             const float* __restrict__ b,
                             unsigned* __restrict__ keys,
                             int npts, int q)     // q = ceil(npts/4)
{
    const int t = blockIdx.x * blockDim.x + threadIdx.x;
    const int point = t >> 3;
    const int lane8 = t & 7;
    if (point >= q) return;

    const int p1 = point + q;
    const int p2 = point + 2 * q;
    const int p3 = point + 3 * q;
    const bool h1 = (p1 < npts), h2 = (p2 < npts), h3 = (p3 < npts);

    const float4 wv = __ldg((const float4*)w + lane8);
    const float4 x0 = __ldg((const float4*)(x + (size_t)point * DFEAT) + lane8);
    float4 x1 = make_float4(0.f, 0.f, 0.f, 0.f);
    float4 x2 = make_float4(0.f, 0.f, 0.f, 0.f);
    float4 x3 = make_float4(0.f, 0.f, 0.f, 0.f);
    if (h1) x1 = __ldg((const float4*)(x + (size_t)p1 * DFEAT) + lane8);
    if (h2) x2 = __ldg((const float4*)(x + (size_t)p2 * DFEAT) + lane8);
    if (h3) x3 = __ldg((const float4*)(x + (size_t)p3 * DFEAT) + lane8);

    float s0 = x0.x * wv.x + x0.y * wv.y + x0.z * wv.z + x0.w * wv.w;
    float s1 = x1.x * wv.x + x1.y * wv.y + x1.z * wv.z + x1.w * wv.w;
    float s2 = x2.x * wv.x + x2.y * wv.y + x2.z * wv.z + x2.w * wv.w;
    float s3 = x3.x * wv.x + x3.y * wv.y + x3.z * wv.z + x3.w * wv.w;

#pragma unroll
    for (int o = 1; o <= 4; o <<= 1) {
        s0 += __shfl_xor_sync(0xffffffffu, s0, o);
        s1 += __shfl_xor_sync(0xffffffffu, s1, o);
        s2 += __shfl_xor_sync(0xffffffffu, s2, o);
        s3 += __shfl_xor_sync(0xffffffffu, s3, o);
    }

    if (lane8 == 0) {
        const float bb = __ldg(b);
        unsigned u0 = __float_as_uint(s0 + bb);
        keys[point] = (u0 & 0x80000000u) ? ~u0 : (u0 | 0x80000000u);
        if (h1) {
            unsigned u = __float_as_uint(s1 + bb);
            keys[p1] = (u & 0x80000000u) ? ~u : (u | 0x80000000u);
        }
        if (h2) {
            unsigned u = __float_as_uint(s2 + bb);
            keys[p2] = (u & 0x80000000u) ? ~u : (u | 0x80000000u);
        }
        if (h3) {
            unsigned u = __float_as_uint(s3 + bb);
            keys[p3] = (u & 0x80000000u) ? ~u : (u | 0x80000000u);
        }
    }
}

// ---------------------------------------------------------------------------
// Kernel 2: histogram (4 CTAs/segment) + last-block threshold scan.
// ---------------------------------------------------------------------------
__global__ __launch_bounds__(1024, 1)
void hist_kernel(const unsigned* __restrict__ keys, int L)
{
    const int seg = blockIdx.x / CPS;
    const int c   = blockIdx.x % CPS;
    const unsigned* __restrict__ k = keys + (size_t)seg * L;
    unsigned* __restrict__ h    = g_work + (size_t)seg * HBINS;
    unsigned* __restrict__ done = g_work + (size_t)MAXB * HBINS;

    __shared__ unsigned s_h[HBINS];
    __shared__ unsigned s_w[32];
    __shared__ int s_last, s_D;
    __shared__ unsigned s_kk;

    const int tid  = threadIdx.x;
    const int lane = tid & 31;
    const int wid  = tid >> 5;
#pragma unroll
    for (int j = 0; j < HBINS / 1024; j++) s_h[tid + j * 1024] = 0u;
    __syncthreads();

    const int nvec = L >> 2;
    const int tail = nvec << 2;
    const int chunk = (nvec + CPS - 1) / CPS;
    const int vbeg = c * chunk;
    const int vend = min(nvec, vbeg + chunk);

#pragma unroll 4
    for (int i = vbeg + tid; i < vend; i += 1024) {
        const uint4 kv = __ldg((const uint4*)k + i);
        atomicAdd(&s_h[kv.x >> 20], 1u);
        atomicAdd(&s_h[kv.y >> 20], 1u);
        atomicAdd(&s_h[kv.z >> 20], 1u);
        atomicAdd(&s_h[kv.w >> 20], 1u);
    }
    if (c == CPS - 1) {
        for (int i = tail + tid; i < L; i += 1024)
            atomicAdd(&s_h[__ldg(k + i) >> 20], 1u);
    }
    __syncthreads();

#pragma unroll
    for (int j = 0; j < HBINS / 1024; j++) {
        const unsigned v = s_h[tid + j * 1024];
        if (v) atomicAdd(&h[tid + j * 1024], v);      // RED, distinct addresses
    }
    __threadfence();
    if (tid == 0) s_last = (atomicAdd(&done[seg], 1u) == CPS - 1);
    __syncthreads();
    if (!s_last) return;
    __threadfence();

    // last CTA of this segment: reload complete hist (L2, bypass L1) + scan
#pragma unroll
    for (int j = 0; j < HBINS / 1024; j++)
        s_h[tid + j * 1024] = __ldcg(h + tid + j * 1024);
    __syncthreads();
    find_threshold_bin(s_h, s_w, tid, lane, wid, &s_D, &s_kk);
    if (tid == 0) {
        g_thresh[2 * seg]     = (unsigned)s_D;
        g_thresh[2 * seg + 1] = s_kk;
    }
}

// ---------------------------------------------------------------------------
// Kernel 3: compaction, 4 CTAs/segment -> global winner/candidate lists.
// ---------------------------------------------------------------------------
__global__ __launch_bounds__(1024, 1)
void compact_kernel(const unsigned* __restrict__ keys, int L)
{
    const int seg = blockIdx.x / CPC;
    const int c   = blockIdx.x % CPC;
    const unsigned* __restrict__ k = keys + (size_t)seg * L;
    unsigned* __restrict__ nsel  = g_work + (size_t)MAXB * HBINS + MAXB;
    unsigned* __restrict__ ncand = g_work + (size_t)MAXB * HBINS + 2 * MAXB;
    int*      __restrict__ sel  = g_sel     + (size_t)seg * TOPK;
    unsigned* __restrict__ cKey = g_candKey + (size_t)seg * CAND_G;
    int*      __restrict__ cIdx = g_candIdx + (size_t)seg * CAND_G;

    const unsigned D = __ldg(&g_thresh[2 * seg]);
    const unsigned hiD  = D << 20;
    const unsigned hiD1 = hiD + (1u << 20);

    const int tid  = threadIdx.x;
    const int nvec = L >> 2;
    const int tail = nvec << 2;
    const int chunk = (nvec + CPC - 1) / CPC;
    const int vbeg = c * chunk;
    const int vend = min(nvec, vbeg + chunk);

#pragma unroll 4
    for (int i = vbeg + tid; i < vend; i += 1024) {
        const uint4 kv = __ldg((const uint4*)k + i);
        const int base = i << 2;
        const unsigned ks[4] = {kv.x, kv.y, kv.z, kv.w};
#pragma unroll
        for (int cc = 0; cc < 4; cc++) {
            const unsigned key = ks[cc];
            if (key >= hiD) {                        // RARE (~3%)
                if (key >= hiD1) {
                    const unsigned p = atomicAdd(&nsel[seg], 1u);
                    if (p < TOPK) sel[p] = base + cc;
                } else {
                    const unsigned p = atomicAdd(&ncand[seg], 1u);
                    if (p < CAND_G) { cKey[p] = key; cIdx[p] = base + cc; }
                }
            }
        }
    }
    if (c == CPC - 1) {
        for (int i = tail + tid; i < L; i += 1024) {
            const unsigned key = __ldg(k + i);
            if (key >= hiD) {
                if (key >= hiD1) {
                    const unsigned p = atomicAdd(&nsel[seg], 1u);
                    if (p < TOPK) sel[p] = i;
                } else {
                    const unsigned p = atomicAdd(&ncand[seg], 1u);
                    if (p < CAND_G) { cKey[p] = key; cIdx[p] = i; }
                }
            }
        }
    }
}

// ---------------------------------------------------------------------------
// Kernel 4: finalize selection (tiny): radix over ~hundreds of candidates,
// tie-break, append to g_sel, write total count.
// ---------------------------------------------------------------------------
__global__ __launch_bounds__(256, 4)
void final_kernel(int L)
{
    const int b = blockIdx.x;
    const unsigned* __restrict__ nselg  = g_work + (size_t)MAXB * HBINS + MAXB;
    const unsigned* __restrict__ ncandg = g_work + (size_t)MAXB * HBINS + 2 * MAXB;
    const unsigned* __restrict__ cKeyG = g_candKey + (size_t)b * CAND_G;
    const int*      __restrict__ cIdxG = g_candIdx + (size_t)b * CAND_G;
    int* __restrict__ sel = g_sel + (size_t)b * TOPK;

    __shared__ unsigned candKey[CAND_G];
    __shared__ int      candIdx[CAND_G];
    __shared__ int      eqIdx[EQ_CAP];
    __shared__ unsigned cnt[256];
    __shared__ unsigned s_tkey, s_kk2;
    __shared__ int      s_napp, s_neq;

    const int tid = threadIdx.x;
    const unsigned D  = g_thresh[2 * b];
    const unsigned kk = g_thresh[2 * b + 1];
    const int n1raw = (int)nselg[b];
    const int n1 = (n1raw < TOPK) ? n1raw : TOPK;
    int nc = (int)ncandg[b];
    if (nc > CAND_G) nc = CAND_G;

    for (int j = tid; j < nc; j += 256) {
        candKey[j] = __ldg(cKeyG + j);
        candIdx[j] = __ldg(cIdxG + j);
    }
    if (tid == 0) { s_tkey = D << 20; s_kk2 = kk; s_napp = 0; s_neq = 0; }
    __syncthreads();

    // ---- 3-pass radix on the low 20 bits over smem candidates ----
    const int shifts[3] = {12, 4, 0};
    const int widths[3] = {8, 8, 4};
    for (int p = 0; p < 3; p++) {
        const int sh = shifts[p], wd = widths[p];
        const unsigned maskAbove = ~((1u << (sh + wd)) - 1u);
        const unsigned bins = 1u << wd;
        cnt[tid] = 0u;
        __syncthreads();
        const unsigned pref = s_tkey;
        for (int j = tid; j < nc; j += 256) {
            const unsigned key = candKey[j];
            if ((key & maskAbove) == pref)
                atomicAdd(&cnt[(key >> sh) & (bins - 1u)], 1u);
        }
        __syncthreads();
        if (tid == 0) {
            unsigned kk2 = s_kk2;
            for (int d = (int)bins - 1; d >= 0; d--) {
                const unsigned c = cnt[d];
                if (kk2 <= c) { s_tkey = pref | ((unsigned)d << sh); break; }
                kk2 -= c;
            }
            s_kk2 = kk2;
        }
        __syncthreads();
    }
    const unsigned t = s_tkey;

    // append candidates > t; collect == t
    for (int j = tid; j < nc; j += 256) {
        const unsigned key = candKey[j];
        if (key > t) {
            const int p = atomicAdd(&s_napp, 1);
            if (n1 + p < TOPK) sel[n1 + p] = candIdx[j];
        } else if (key == t) {
            const int p = atomicAdd(&s_neq, 1);
            if (p < EQ_CAP) eqIdx[p] = candIdx[j];
        }
    }
    __syncthreads();

    if (tid == 0) {
        int kk_t = (int)s_kk2;
        const int neq = (s_neq < EQ_CAP) ? s_neq : EQ_CAP;
        if (kk_t > neq) kk_t = neq;
        const int base = n1 + s_napp;
        for (int j = 0; j < kk_t; j++) {
            int mi = j;
            for (int m = j + 1; m < neq; m++)
                if (eqIdx[m] < eqIdx[mi]) mi = m;
            const int tmp = eqIdx[j]; eqIdx[j] = eqIdx[mi]; eqIdx[mi] = tmp;
            if (base + j < TOPK) sel[base + j] = eqIdx[j];
        }
        int total = base + kk_t;
        g_nseltot[b] = (total < TOPK) ? total : TOPK;
    }
}

// ---------------------------------------------------------------------------
// Kernel 5: gather partial sums, GPS CTAs/segment x 256 threads.
// ---------------------------------------------------------------------------
__global__ __launch_bounds__(256, 4)
void gather_kernel(const float* __restrict__ x,
                   float* __restrict__ part,
                   int L)
{
    const int b = blockIdx.x / GPS;
    const int c = blockIdx.x % GPS;
    const float* __restrict__ xb = x + (size_t)b * L * DFEAT;
    const int* __restrict__ sel = g_sel + (size_t)b * TOPK;

    __shared__ float red[8][33];
    const int tid  = threadIdx.x;
    const int lane = tid & 31;
    const int wid  = tid >> 5;            // 0..7

    const int n = g_nseltot[b];
    const int span = TOPK / GPS;          // 128
    const int cbeg = c * span;
    const int jbeg = cbeg + wid * (span / 8);
    const int jend = min(n, min(jbeg + span / 8, cbeg + span));

    float a0 = 0.f, a1 = 0.f, a2 = 0.f, a3 = 0.f;
    float a4 = 0.f, a5 = 0.f, a6 = 0.f, a7 = 0.f;
    int j = jbeg;
    for (; j + 7 < jend; j += 8) {
        a0 += __ldg(xb + (size_t)__ldg(sel + j + 0) * DFEAT + lane);
        a1 += __ldg(xb + (size_t)__ldg(sel + j + 1) * DFEAT + lane);
        a2 += __ldg(xb + (size_t)__ldg(sel + j + 2) * DFEAT + lane);
        a3 += __ldg(xb + (size_t)__ldg(sel + j + 3) * DFEAT + lane);
        a4 += __ldg(xb + (size_t)__ldg(sel + j + 4) * DFEAT + lane);
        a5 += __ldg(xb + (size_t)__ldg(sel + j + 5) * DFEAT + lane);
        a6 += __ldg(xb + (size_t)__ldg(sel + j + 6) * DFEAT + lane);
        a7 += __ldg(xb + (size_t)__ldg(sel + j + 7) * DFEAT + lane);
    }
    for (; j < jend; j++)
        a0 += __ldg(xb + (size_t)__ldg(sel + j) * DFEAT + lane);
    red[wid][lane] = ((a0 + a1) + (a2 + a3)) + ((a4 + a5) + (a6 + a7));
    __syncthreads();

    if (wid == 0) {
        float v = 0.f;
#pragma unroll
        for (int ww = 0; ww < 8; ww++) v += red[ww][lane];
        part[((size_t)b * GPS + c) * DFEAT + lane] = v;
    }
}

// ---------------------------------------------------------------------------
// Kernel 6: combine partials, /L, L2 normalize. One warp per segment.
// ---------------------------------------------------------------------------
__global__ void normalize_kernel(const float* __restrict__ part,
                                 float* __restrict__ out,
                                 int L)
{
    const int b = blockIdx.x;
    const int lane = threadIdx.x;          // 0..31

    float v = 0.f;
#pragma unroll
    for (int c = 0; c < GPS; c++)
        v += part[((size_t)b * GPS + c) * DFEAT + lane];
    v /= (float)L;

    float ss = v * v;
#pragma unroll
    for (int o = 16; o; o >>= 1) ss += __shfl_xor_sync(0xffffffffu, ss, o);
    const float norm = sqrtf(ss);
    out[b * DFEAT + lane] = v / fmaxf(norm, 1e-12f);
}

extern "C" void kernel_launch(void* const* d_in, const int* in_sizes, int n_in,
                              void* d_out, int out_size)
{
    const float* x  = (const float*)d_in[0];   // [B*L, 32] fp32
    const float* w  = (const float*)d_in[2];   // [32]
    const float* bb = (const float*)d_in[3];   // [1]
    float* out = (float*)d_out;                // [B, 32]

    const int B = in_sizes[1];
    const int L = in_sizes[0] / (B * DFEAT);
    const int npts = B * L;
    const int q = (npts + 3) / 4;

    unsigned *keys = nullptr, *work = nullptr;
    float *part = nullptr;
    cudaGetSymbolAddress((void**)&keys, g_keys);
    cudaGetSymbolAddress((void**)&work, g_work);
    cudaGetSymbolAddress((void**)&part, g_part);

    // one memset: hist (B*HBINS used) + all counters (at fixed MAXB offsets)
    cudaMemsetAsync(work, 0, ((size_t)MAXB * HBINS + 3 * MAXB) * sizeof(unsigned));

    {
        const int threads = 256;
        const long long total = (long long)q * 8;
        const int grid = (int)((total + threads - 1) / threads);
        score_kernel<<<grid, threads>>>(x, w, bb, keys, npts, q);
    }
    hist_kernel<<<B * CPS, 1024>>>(keys, L);
    compact_kernel<<<B * CPC, 1024>>>(keys, L);
    final_kernel<<<B, 256>>>(L);
    gather_kernel<<<B * GPS, 256>>>(x, part, L);
    normalize_kernel<<<B, 32>>>(part, out, L);
}

// round 14
// speedup vs baseline: 1.3790x; 1.3790x over previous
#include <cuda_runtime.h>
#include <math.h>

#define TOPK     1024
#define DFEAT    32
#define HBINS    4096          // top-12-bit histogram
#define CAND_CAP 2048
#define EQ_CAP   1024
#define MAXB     256
#define CPS      8             // histogram CTAs per segment
#define GPS      8             // gather CTAs per segment

__device__ unsigned g_keys[4000000];
__device__ unsigned g_hist[MAXB * HBINS];
__device__ int      g_sel[MAXB * TOPK];
__device__ int      g_nseltot[MAXB];
__device__ float    g_part[MAXB * GPS * DFEAT];

// ---------------------------------------------------------------------------
// Kernel 1: score (R10 form, 64.4us @ 82.9% DRAM). Unchanged.
// ---------------------------------------------------------------------------
__global__ void score_kernel(const float* __restrict__ x,
                             const float* __restrict__ w,
                             const float* __restrict__ b,
                             unsigned* __restrict__ keys,
                             int npts, int q)     // q = ceil(npts/4)
{
    const int t = blockIdx.x * blockDim.x + threadIdx.x;
    const int point = t >> 3;
    const int lane8 = t & 7;
    if (point >= q) return;

    const int p1 = point + q;
    const int p2 = point + 2 * q;
    const int p3 = point + 3 * q;
    const bool h1 = (p1 < npts), h2 = (p2 < npts), h3 = (p3 < npts);

    const float4 wv = __ldg((const float4*)w + lane8);
    const float4 x0 = __ldg((const float4*)(x + (size_t)point * DFEAT) + lane8);
    float4 x1 = make_float4(0.f, 0.f, 0.f, 0.f);
    float4 x2 = make_float4(0.f, 0.f, 0.f, 0.f);
    float4 x3 = make_float4(0.f, 0.f, 0.f, 0.f);
    if (h1) x1 = __ldg((const float4*)(x + (size_t)p1 * DFEAT) + lane8);
    if (h2) x2 = __ldg((const float4*)(x + (size_t)p2 * DFEAT) + lane8);
    if (h3) x3 = __ldg((const float4*)(x + (size_t)p3 * DFEAT) + lane8);

    float s0 = x0.x * wv.x + x0.y * wv.y + x0.z * wv.z + x0.w * wv.w;
    float s1 = x1.x * wv.x + x1.y * wv.y + x1.z * wv.z + x1.w * wv.w;
    float s2 = x2.x * wv.x + x2.y * wv.y + x2.z * wv.z + x2.w * wv.w;
    float s3 = x3.x * wv.x + x3.y * wv.y + x3.z * wv.z + x3.w * wv.w;

#pragma unroll
    for (int o = 1; o <= 4; o <<= 1) {
        s0 += __shfl_xor_sync(0xffffffffu, s0, o);
        s1 += __shfl_xor_sync(0xffffffffu, s1, o);
        s2 += __shfl_xor_sync(0xffffffffu, s2, o);
        s3 += __shfl_xor_sync(0xffffffffu, s3, o);
    }

    if (lane8 == 0) {
        const float bb = __ldg(b);
        unsigned u0 = __float_as_uint(s0 + bb);
        keys[point] = (u0 & 0x80000000u) ? ~u0 : (u0 | 0x80000000u);
        if (h1) {
            unsigned u = __float_as_uint(s1 + bb);
            keys[p1] = (u & 0x80000000u) ? ~u : (u | 0x80000000u);
        }
        if (h2) {
            unsigned u = __float_as_uint(s2 + bb);
            keys[p2] = (u & 0x80000000u) ? ~u : (u | 0x80000000u);
        }
        if (h3) {
            unsigned u = __float_as_uint(s3 + bb);
            keys[p3] = (u & 0x80000000u) ? ~u : (u | 0x80000000u);
        }
    }
}

// ---------------------------------------------------------------------------
// Kernel 1b: CTA-aggregated histogram, CPS CTAs/segment (plain smem atomics).
// ---------------------------------------------------------------------------
__global__ __launch_bounds__(1024, 1)
void hist_kernel(const unsigned* __restrict__ keys,
                 unsigned* __restrict__ hist,
                 int L)
{
    const int seg = blockIdx.x / CPS;
    const int c   = blockIdx.x % CPS;
    const unsigned* __restrict__ k = keys + (size_t)seg * L;
    unsigned* __restrict__ h = hist + (size_t)seg * HBINS;

    __shared__ unsigned s_h[HBINS];
    const int tid = threadIdx.x;
#pragma unroll
    for (int j = 0; j < HBINS / 1024; j++) s_h[tid + j * 1024] = 0u;
    __syncthreads();

    const int nvec = L >> 2;
    const int tail = nvec << 2;
    const int chunk = (nvec + CPS - 1) / CPS;
    const int vbeg = c * chunk;
    const int vend = min(nvec, vbeg + chunk);

#pragma unroll 4
    for (int i = vbeg + tid; i < vend; i += 1024) {
        const uint4 kv = __ldg((const uint4*)k + i);
        atomicAdd(&s_h[kv.x >> 20], 1u);
        atomicAdd(&s_h[kv.y >> 20], 1u);
        atomicAdd(&s_h[kv.z >> 20], 1u);
        atomicAdd(&s_h[kv.w >> 20], 1u);
    }
    if (c == CPS - 1) {
        for (int i = tail + tid; i < L; i += 1024)
            atomicAdd(&s_h[__ldg(k + i) >> 20], 1u);
    }
    __syncthreads();

#pragma unroll
    for (int j = 0; j < HBINS / 1024; j++) {
        const unsigned v = s_h[tid + j * 1024];
        if (v) atomicAdd(&h[tid + j * 1024], v);      // RED, distinct addresses
    }
}

// ---------------------------------------------------------------------------
// Kernel 2: selection per segment (64 CTAs x 1024). Writes index list.
// All digit scans are PARALLEL (block-wide suffix scans) — no serial loops.
// ---------------------------------------------------------------------------
__global__ __launch_bounds__(1024, 1)
void select_kernel(const unsigned* __restrict__ keys,
                   const unsigned* __restrict__ hist,
                   int L)
{
    const int b = blockIdx.x;
    const unsigned* __restrict__ k = keys + (size_t)b * L;
    const unsigned* __restrict__ h = hist + (size_t)b * HBINS;

    __shared__ unsigned s_h[HBINS];
    __shared__ unsigned s_w[32];
    __shared__ unsigned cnt[256];
    __shared__ int      selIdx[TOPK];
    __shared__ unsigned candKey[CAND_CAP];
    __shared__ int      candIdx[CAND_CAP];
    __shared__ int      eqIdx[EQ_CAP];
    __shared__ int      s_D, s_nsel, s_ncand, s_neq;
    __shared__ unsigned s_kk, s_tkey, s_kk2;

    const int tid  = threadIdx.x;
    const int lane = tid & 31;
    const int wid  = tid >> 5;

    if (tid == 0) { s_nsel = 0; s_ncand = 0; s_neq = 0; }
#pragma unroll
    for (int j = 0; j < 4; j++) s_h[tid + j * 1024] = __ldg(h + tid + j * 1024);
    __syncthreads();

    // ---- suffix scan over 4096 bins: find bin D and in-bin rank kk ----
    {
        const unsigned t4 = s_h[tid * 4] + s_h[tid * 4 + 1]
                          + s_h[tid * 4 + 2] + s_h[tid * 4 + 3];
        unsigned v = t4;
#pragma unroll
        for (int off = 1; off < 32; off <<= 1) {
            unsigned o = __shfl_down_sync(0xffffffffu, v, off);
            if (lane + off < 32) v += o;
        }
        if (lane == 0) s_w[wid] = v;
        __syncthreads();
        if (wid == 0) {
            const unsigned tv = s_w[lane];
            unsigned iv = tv;
#pragma unroll
            for (int off = 1; off < 32; off <<= 1) {
                unsigned o = __shfl_down_sync(0xffffffffu, iv, off);
                if (lane + off < 32) iv += o;
            }
            s_w[lane] = iv - tv;
        }
        __syncthreads();

        const long long E = (long long)s_w[wid] + (long long)(v - t4);
        long long r = (long long)TOPK - E;
        if (r >= 1 && r <= (long long)t4) {
            for (int d = tid * 4 + 3; d >= tid * 4; d--) {
                const unsigned c = s_h[d];
                if (r <= (long long)c) { s_D = d; s_kk = (unsigned)r; break; }
                r -= (long long)c;
            }
        }
        __syncthreads();
    }

    const int D = s_D;
    const unsigned kk = s_kk;
    const unsigned hiD  = (unsigned)D << 20;
    const unsigned hiD1 = hiD + (1u << 20);

    const int nvec = L >> 2;
    const int tail = nvec << 2;

    // ---- pass B: rare-branch compact (~3% of elements pass) ----
#pragma unroll 4
    for (int i = tid; i < nvec; i += 1024) {
        const uint4 kv = __ldg((const uint4*)k + i);
        const int base = i << 2;
        const unsigned ks[4] = {kv.x, kv.y, kv.z, kv.w};
#pragma unroll
        for (int c = 0; c < 4; c++) {
            const unsigned key = ks[c];
            if (key >= hiD) {                        // RARE
                if (key >= hiD1) {
                    const int p = atomicAdd(&s_nsel, 1);
                    if (p < TOPK) selIdx[p] = base + c;
                } else {
                    const int p = atomicAdd(&s_ncand, 1);
                    if (p < CAND_CAP) { candKey[p] = key; candIdx[p] = base + c; }
                }
            }
        }
    }
    for (int i = tail + tid; i < L; i += 1024) {
        const unsigned key = __ldg(k + i);
        if (key >= hiD) {
            if (key >= hiD1) {
                const int p = atomicAdd(&s_nsel, 1);
                if (p < TOPK) selIdx[p] = i;
            } else {
                const int p = atomicAdd(&s_ncand, 1);
                if (p < CAND_CAP) { candKey[p] = key; candIdx[p] = i; }
            }
        }
    }
    __syncthreads();
    const int nc = s_ncand;
    if (tid == 0) { s_tkey = hiD; s_kk2 = kk; }
    __syncthreads();

    // ---- refine low 20 bits (3 radix passes, PARALLEL digit find) ----
    const int shifts[3] = {12, 4, 0};
    const int widths[3] = {8, 8, 4};
    const bool fastPath = (nc <= CAND_CAP);

    for (int p = 0; p < 3; p++) {
        const int sh = shifts[p], wd = widths[p];
        const unsigned maskAbove = ~((1u << (sh + wd)) - 1u);
        const unsigned bins = 1u << wd;
        if (tid < 256) cnt[tid] = 0u;
        __syncthreads();
        const unsigned pref = s_tkey;
        if (fastPath) {
            for (int j = tid; j < nc; j += 1024) {
                const unsigned key = candKey[j];
                if ((key & maskAbove) == pref)
                    atomicAdd(&cnt[(key >> sh) & (bins - 1u)], 1u);
            }
        } else {
            for (int i = tid; i < L; i += 1024) {
                const unsigned key = __ldg(k + i);
                if ((key & maskAbove) == pref)
                    atomicAdd(&cnt[(key >> sh) & (bins - 1u)], 1u);
            }
        }
        __syncthreads();

        // parallel digit find: unique d with S_excl(d) < kk2 <= S_excl(d)+cnt[d]
        const unsigned kk2in = s_kk2;
        const unsigned c = (tid < (int)bins) ? cnt[tid] : 0u;
        unsigned v = c;
#pragma unroll
        for (int off = 1; off < 32; off <<= 1) {
            unsigned o = __shfl_down_sync(0xffffffffu, v, off);
            if (lane + off < 32) v += o;
        }
        if (lane == 0) s_w[wid] = v;
        __syncthreads();
        if (wid == 0) {
            const unsigned tv = s_w[lane];
            unsigned iv = tv;
#pragma unroll
            for (int off = 1; off < 32; off <<= 1) {
                unsigned o = __shfl_down_sync(0xffffffffu, iv, off);
                if (lane + off < 32) iv += o;
            }
            s_w[lane] = iv - tv;
        }
        __syncthreads();
        if (tid < (int)bins) {
            const unsigned Sexcl = s_w[wid] + (v - c);
            if (Sexcl < kk2in && kk2in <= Sexcl + c) {
                s_tkey = pref | ((unsigned)tid << sh);
                s_kk2  = kk2in - Sexcl;
            }
        }
        __syncthreads();
    }
    const unsigned t = s_tkey;

    // ---- final compaction of candidates ----
    if (fastPath) {
        for (int j = tid; j < nc; j += 1024) {
            const unsigned key = candKey[j];
            if (key > t) {
                const int p = atomicAdd(&s_nsel, 1);
                if (p < TOPK) selIdx[p] = candIdx[j];
            } else if (key == t) {
                const int p = atomicAdd(&s_neq, 1);
                if (p < EQ_CAP) eqIdx[p] = candIdx[j];
            }
        }
    } else {
        for (int i = tid; i < L; i += 1024) {
            const unsigned key = __ldg(k + i);
            if (key < hiD || key >= hiD1) continue;
            if (key > t) {
                const int p = atomicAdd(&s_nsel, 1);
                if (p < TOPK) selIdx[p] = i;
            } else if (key == t) {
                const int p = atomicAdd(&s_neq, 1);
                if (p < EQ_CAP) eqIdx[p] = i;
            }
        }
    }
    __syncthreads();

    // ---- ties: take kk_t smallest indices (jax top_k tie-break) ----
    if (tid == 0) {
        int kk_t = (int)s_kk2;
        const int neq = (s_neq < EQ_CAP) ? s_neq : EQ_CAP;
        if (kk_t > neq) kk_t = neq;
        const int base = s_nsel;
        for (int j = 0; j < kk_t; j++) {
            int mi = j;
            for (int m = j + 1; m < neq; m++)
                if (eqIdx[m] < eqIdx[mi]) mi = m;
            const int tmp = eqIdx[j]; eqIdx[j] = eqIdx[mi]; eqIdx[mi] = tmp;
            if (base + j < TOPK) selIdx[base + j] = eqIdx[j];
        }
        const int total = base + kk_t;
        s_nsel = (total < TOPK) ? total : TOPK;
        g_nseltot[b] = s_nsel;
    }
    __syncthreads();

    // ---- export final index list ----
    const int n = s_nsel;
    for (int i = tid; i < n; i += 1024)
        g_sel[(size_t)b * TOPK + i] = selIdx[i];
}

// ---------------------------------------------------------------------------
// Kernel 3: gather partial sums, GPS CTAs/segment x 256 threads.
// ---------------------------------------------------------------------------
__global__ __launch_bounds__(256, 4)
void gather_kernel(const float* __restrict__ x,
                   float* __restrict__ part,
                   int L)
{
    const int b = blockIdx.x / GPS;
    const int c = blockIdx.x % GPS;
    const float* __restrict__ xb = x + (size_t)b * L * DFEAT;
    const int* __restrict__ sel = g_sel + (size_t)b * TOPK;

    __shared__ float red[8][33];
    const int tid  = threadIdx.x;
    const int lane = tid & 31;
    const int wid  = tid >> 5;            // 0..7

    const int n = g_nseltot[b];
    const int span = TOPK / GPS;          // 128
    const int cbeg = c * span;
    const int jbeg = cbeg + wid * (span / 8);
    const int jend = min(n, min(jbeg + span / 8, cbeg + span));

    float a0 = 0.f, a1 = 0.f, a2 = 0.f, a3 = 0.f;
    float a4 = 0.f, a5 = 0.f, a6 = 0.f, a7 = 0.f;
    int j = jbeg;
    for (; j + 7 < jend; j += 8) {
        a0 += __ldg(xb + (size_t)__ldg(sel + j + 0) * DFEAT + lane);
        a1 += __ldg(xb + (size_t)__ldg(sel + j + 1) * DFEAT + lane);
        a2 += __ldg(xb + (size_t)__ldg(sel + j + 2) * DFEAT + lane);
        a3 += __ldg(xb + (size_t)__ldg(sel + j + 3) * DFEAT + lane);
        a4 += __ldg(xb + (size_t)__ldg(sel + j + 4) * DFEAT + lane);
        a5 += __ldg(xb + (size_t)__ldg(sel + j + 5) * DFEAT + lane);
        a6 += __ldg(xb + (size_t)__ldg(sel + j + 6) * DFEAT + lane);
        a7 += __ldg(xb + (size_t)__ldg(sel + j + 7) * DFEAT + lane);
    }
    for (; j < jend; j++)
        a0 += __ldg(xb + (size_t)__ldg(sel + j) * DFEAT + lane);
    red[wid][lane] = ((a0 + a1) + (a2 + a3)) + ((a4 + a5) + (a6 + a7));
    __syncthreads();

    if (wid == 0) {
        float v = 0.f;
#pragma unroll
        for (int ww = 0; ww < 8; ww++) v += red[ww][lane];
        part[((size_t)b * GPS + c) * DFEAT + lane] = v;
    }
}

// ---------------------------------------------------------------------------
// Kernel 4: combine partials, /L, L2 normalize. One warp per segment.
// ---------------------------------------------------------------------------
__global__ void normalize_kernel(const float* __restrict__ part,
                                 float* __restrict__ out,
                                 int L)
{
    const int b = blockIdx.x;
    const int lane = threadIdx.x;          // 0..31

    float v = 0.f;
#pragma unroll
    for (int c = 0; c < GPS; c++)
        v += part[((size_t)b * GPS + c) * DFEAT + lane];
    v /= (float)L;

    float ss = v * v;
#pragma unroll
    for (int o = 16; o; o >>= 1) ss += __shfl_xor_sync(0xffffffffu, ss, o);
    const float norm = sqrtf(ss);
    out[b * DFEAT + lane] = v / fmaxf(norm, 1e-12f);
}

extern "C" void kernel_launch(void* const* d_in, const int* in_sizes, int n_in,
                              void* d_out, int out_size)
{
    const float* x  = (const float*)d_in[0];   // [B*L, 32] fp32
    const float* w  = (const float*)d_in[2];   // [32]
    const float* bb = (const float*)d_in[3];   // [1]
    float* out = (float*)d_out;                // [B, 32]

    const int B = in_sizes[1];
    const int L = in_sizes[0] / (B * DFEAT);
    const int npts = B * L;
    const int q = (npts + 3) / 4;

    unsigned *keys = nullptr, *hist = nullptr;
    float *part = nullptr;
    cudaGetSymbolAddress((void**)&keys, g_keys);
    cudaGetSymbolAddress((void**)&hist, g_hist);
    cudaGetSymbolAddress((void**)&part, g_part);

    cudaMemsetAsync(hist, 0, (size_t)B * HBINS * sizeof(unsigned));

    {
        const int threads = 256;
        const long long total = (long long)q * 8;
        const int grid = (int)((total + threads - 1) / threads);
        score_kernel<<<grid, threads>>>(x, w, bb, keys, npts, q);
    }
    hist_kernel<<<B * CPS, 1024>>>(keys, hist, L);
    select_kernel<<<B, 1024>>>(keys, hist, L);
    gather_kernel<<<B * GPS, 256>>>(x, part, L);
    normalize_kernel<<<B, 32>>>(part, out, L);
}